// round 12
// baseline (speedup 1.0000x reference)
#include <cuda_runtime.h>
#include <cstdint>

// Problem constants (fixed by the reference).
#define BB   4
#define DD   128
#define HH   128
#define WW   128
#define NMAX 500000
#define CIN  32
#define COUT 32
#define KVOL 125
#define GRID_SZ (BB * DD * HH * WW)   // 8,388,608
#define NBUCK (GRID_SZ / 512)         // 16384 buckets of 512 voxels (4 x-rows)
#define EPSV 1e-4f
#define FULLMASK 0xffffffffu
#define SITES_PER_BLOCK 2048          // 256 threads x 8 site-iterations

// -------- device scratch (allocation-free: static __device__ globals) --------
// g_grid holds rank+1 (0 = inactive). Device globals are zero-initialized at
// module load; k_cleanup restores the all-zero state after every run, so no
// full-grid reset kernel is needed.
__device__ int   g_grid[GRID_SZ];
__device__ int   g_flat[NMAX];             // site (original order) -> flat idx
__device__ int   g_sflat[NMAX];            // rank -> flat idx (bucket-sorted)
__device__ int   g_orig[NMAX];             // rank -> original site row
__device__ int   g_hist[NBUCK];            // bucket histogram / scan bases
__device__ __align__(16) float g_feat[(size_t)NMAX * CIN]; // rank-ordered feats
__device__ __align__(16) float g_acc[(size_t)NMAX * CIN];  // rank-ordered accum
__device__ float g_stats[2 * CIN];

// f32x2 packed FMA — PTX only.
#define FFMA2(acc, f2, w2) \
    asm("fma.rn.f32x2 %0, %1, %2, %3;" : "=l"(acc) : "l"(f2), "l"(w2), "l"(acc))

// -------- launch 0: scatter flat ids + bucket histogram + BN stats ----------
__global__ void k_scatter_stats(const float* __restrict__ x,
                                const int* __restrict__ coords, int Nv) {
    int tid = threadIdx.x;
    int i0 = blockIdx.x * blockDim.x + tid;
    int stride = gridDim.x * blockDim.x;   // multiple of 32

    for (int i = i0; i < Nv; i += stride) {
        int4 c = reinterpret_cast<const int4*>(coords)[i];  // b, z, y, x
        int fl = (((c.x * DD + c.y) * HH + c.z) * WW) + c.w;
        g_flat[i] = fl;
        atomicAdd(&g_hist[fl >> 9], 1);
    }

    // per-channel sum / sumsq (lane channel fixed since stride % 32 == 0)
    __shared__ float ss[8][33];
    __shared__ float ss2[8][33];
    int c = tid & 31;
    int wid = tid >> 5;
    float s = 0.f, s2 = 0.f;
    int total = Nv * CIN;
    for (int e = i0; e < total; e += stride) {
        float v = x[e];
        s += v;
        s2 += v * v;
    }
    ss[wid][c] = s;
    ss2[wid][c] = s2;
    __syncthreads();
    if (tid < 32) {
        float a = 0.f, b = 0.f;
#pragma unroll
        for (int k = 0; k < 8; k++) { a += ss[k][tid]; b += ss2[k][tid]; }
        atomicAdd(&g_stats[tid], a);
        atomicAdd(&g_stats[32 + tid], b);
    }
}

// -------- launch 1: exclusive scan of the bucket histogram ------------------
__global__ void __launch_bounds__(1024) k_scan() {
    __shared__ int part[1024];
    int tid = threadIdx.x;
    int local[16];
    int s = 0;
#pragma unroll
    for (int k = 0; k < 16; k++) { local[k] = s; s += g_hist[tid * 16 + k]; }
    part[tid] = s;
    __syncthreads();
    for (int d = 1; d < 1024; d <<= 1) {
        int v = (tid >= d) ? part[tid - d] : 0;
        __syncthreads();
        part[tid] += v;
        __syncthreads();
    }
    int base = (tid == 0) ? 0 : part[tid - 1];
#pragma unroll
    for (int k = 0; k < 16; k++) g_hist[tid * 16 + k] = base + local[k];
}

// -------- launch 2: assign ranks + grid(rank+1) + normalized rank feats -----
__global__ void __launch_bounds__(256) k_rank_norm(const float* __restrict__ x,
                                                   const float* __restrict__ gamma,
                                                   const float* __restrict__ beta,
                                                   int Nv) {
    __shared__ float sc[32], bi[32];
    __shared__ int rr[256];
    int t = threadIdx.x;
    if (t < 32) {
        float invN = 1.0f / (float)Nv;
        float mean = g_stats[t] * invN;
        float var = g_stats[32 + t] * invN - mean * mean;
        float s = gamma[t] * rsqrtf(var + EPSV);
        sc[t] = s;
        bi[t] = beta[t] - mean * s;
    }
    int i = blockIdx.x * 256 + t;
    if (i < Nv) {
        int fl = g_flat[i];
        int r = atomicAdd(&g_hist[fl >> 9], 1);
        g_sflat[r] = fl;
        g_orig[r] = i;
        g_grid[fl] = r + 1;
        rr[t] = r;
    }
    __syncthreads();
#pragma unroll
    for (int k = 0; k < 8; k++) {
        int e = k * 256 + t;                 // float4 unit within block's span
        int slot = e >> 3, q = e & 7;
        int ii = blockIdx.x * 256 + slot;
        if (ii < Nv) {
            float4 v = __ldg(reinterpret_cast<const float4*>(x) + (size_t)ii * 8 + q);
            int c0 = q * 4;
            float4 o;
            o.x = fmaxf(fmaf(v.x, sc[c0 + 0], bi[c0 + 0]), 0.f);
            o.y = fmaxf(fmaf(v.y, sc[c0 + 1], bi[c0 + 1]), 0.f);
            o.z = fmaxf(fmaf(v.z, sc[c0 + 2], bi[c0 + 2]), 0.f);
            o.w = fmaxf(fmaf(v.w, sc[c0 + 3], bi[c0 + 3]), 0.f);
            reinterpret_cast<float4*>(g_feat)[(size_t)rr[slot] * 8 + q] = o;
        }
    }
}

// -------- launch 3 (PROFILED SLOT): sparse conv, one offset per blockIdx.y --
// R7/R8-proven body + software pipelining: the dependent sflat->grid lookup
// chain for site-iteration it+1 is issued before processing iteration it, so
// its ~500cyc latency overlaps the batch work instead of being exposed.
__global__ void __launch_bounds__(256) k_conv(const float* __restrict__ weight,
                                              int Nv) {
    const int o = blockIdx.y;
    const int dz = o / 25 - 2;
    const int dy = (o / 5) % 5 - 2;
    const int dx = o % 5 - 2;
    const int doff = dz * (HH * WW) + dy * WW + dx;
    const int lane = threadIdx.x & 31;
    const int wid = threadIdx.x >> 5;

    __shared__ __align__(16) float tile[2][8][4][32];

    // Packed weight column: w2[t] = (W[2t][lane], W[2t+1][lane]); once / block.
    unsigned long long w2[16];
    {
        const float* wp = weight + o * (CIN * COUT) + lane;
#pragma unroll
        for (int t = 0; t < 16; t++) {
            float a = __ldg(wp + (2 * t) * COUT);
            float b = __ldg(wp + (2 * t + 1) * COUT);
            asm("mov.b64 %0, {%1, %2};" : "=l"(w2[t]) : "f"(a), "f"(b));
        }
    }

    const int p  = lane >> 3;        // which of the 4 batched pairs this lane stores
    const int c4 = (lane & 7) * 4;   // cout base for the vector RED
    int buf = 0;

    const int warpBase0 = blockIdx.x * SITES_PER_BLOCK + wid * 32;

    // ---- pipelined neighbor lookup ----
    auto lookup = [&](int site) -> int {
        int nidx = -1;
        if (site < Nv) {
            int fl = __ldg(&g_sflat[site]);
            int z = (fl >> 14) & 127, y = (fl >> 7) & 127, x = fl & 127;
            if (((unsigned)(z + dz) < 128u) & ((unsigned)(y + dy) < 128u) &
                ((unsigned)(x + dx) < 128u)) {
                nidx = __ldg(&g_grid[fl + doff]) - 1;   // rank or -1
            }
        }
        return nidx;
    };

    int nidx_cur = lookup(warpBase0 + lane);

#pragma unroll 1
    for (int it = 0; it < SITES_PER_BLOCK / 256; it++) {
        const int base = warpBase0 + it * 256;
        // Prefetch next iteration's lookup chain (overlaps batch processing).
        int nidx_next = -1;
        if (it + 1 < SITES_PER_BLOCK / 256)
            nidx_next = lookup(base + 256 + lane);

        unsigned mask = __ballot_sync(FULLMASK, nidx_cur >= 0);
        while (mask) {
            int js0, js1 = 0, js2 = 0, js3 = 0, cnt = 1;
            js0 = __ffs(mask) - 1; mask &= mask - 1;
            if (mask) { js1 = __ffs(mask) - 1; mask &= mask - 1; cnt = 2; }
            if (mask) { js2 = __ffs(mask) - 1; mask &= mask - 1; cnt = 3; }
            if (mask) { js3 = __ffs(mask) - 1; mask &= mask - 1; cnt = 4; }

            int n0 = __shfl_sync(FULLMASK, nidx_cur, js0);
            int n1 = __shfl_sync(FULLMASK, nidx_cur, js1);
            int n2 = __shfl_sync(FULLMASK, nidx_cur, js2);
            int n3 = __shfl_sync(FULLMASK, nidx_cur, js3);
            if (cnt < 2) n1 = n0;
            if (cnt < 3) n2 = n0;
            if (cnt < 4) n3 = n0;

            const ulonglong2* f0 = reinterpret_cast<const ulonglong2*>(g_feat + (size_t)n0 * CIN);
            const ulonglong2* f1 = reinterpret_cast<const ulonglong2*>(g_feat + (size_t)n1 * CIN);
            const ulonglong2* f2 = reinterpret_cast<const ulonglong2*>(g_feat + (size_t)n2 * CIN);
            const ulonglong2* f3 = reinterpret_cast<const ulonglong2*>(g_feat + (size_t)n3 * CIN);

            unsigned long long a0 = 0ull, a1 = 0ull, a2 = 0ull, a3 = 0ull;
#pragma unroll
            for (int k = 0; k < 8; k++) {
                ulonglong2 q0 = f0[k], q1 = f1[k], q2 = f2[k], q3 = f3[k];
                FFMA2(a0, q0.x, w2[2 * k]); FFMA2(a0, q0.y, w2[2 * k + 1]);
                FFMA2(a1, q1.x, w2[2 * k]); FFMA2(a1, q1.y, w2[2 * k + 1]);
                FFMA2(a2, q2.x, w2[2 * k]); FFMA2(a2, q2.y, w2[2 * k + 1]);
                FFMA2(a3, q3.x, w2[2 * k]); FFMA2(a3, q3.y, w2[2 * k + 1]);
            }
            float r0, r1, r2, r3;
            {
                float lo, hi;
                asm("mov.b64 {%0, %1}, %2;" : "=f"(lo), "=f"(hi) : "l"(a0)); r0 = lo + hi;
                asm("mov.b64 {%0, %1}, %2;" : "=f"(lo), "=f"(hi) : "l"(a1)); r1 = lo + hi;
                asm("mov.b64 {%0, %1}, %2;" : "=f"(lo), "=f"(hi) : "l"(a2)); r2 = lo + hi;
                asm("mov.b64 {%0, %1}, %2;" : "=f"(lo), "=f"(hi) : "l"(a3)); r3 = lo + hi;
            }
            if (cnt < 2) r1 = 0.f;
            if (cnt < 3) r2 = 0.f;
            if (cnt < 4) r3 = 0.f;

            // Transpose through smem: [pair][cout] tile, conflict-free.
            tile[buf][wid][0][lane] = r0;
            tile[buf][wid][1][lane] = r1;
            tile[buf][wid][2][lane] = r2;
            tile[buf][wid][3][lane] = r3;
            __syncwarp(FULLMASK);
            float4 v = *reinterpret_cast<const float4*>(&tile[buf][wid][p][c4]);
            if (p < cnt) {
                int jp = (p == 0) ? js0 : (p == 1) ? js1 : (p == 2) ? js2 : js3;
                float* dst = g_acc + (size_t)(base + jp) * COUT + c4;
                // volatile but NO memory clobber: g_acc aliases nothing read
                // here, so later batches' loads may be hoisted above the RED.
                asm volatile("red.global.add.v4.f32 [%0], {%1, %2, %3, %4};"
                             :: "l"(dst), "f"(v.x), "f"(v.y), "f"(v.z), "f"(v.w));
            }
            buf ^= 1;   // double buffer: next STS goes to the other tile
        }
        nidx_cur = nidx_next;
    }
}

// -------- launch 4: permute accumulator back to original row order ----------
__global__ void k_permute(float* __restrict__ out, int Nv) {
    int e = blockIdx.x * blockDim.x + threadIdx.x;  // float4 units
    int total = Nv * (CIN / 4);
    if (e < total) {
        int r = e >> 3, q = e & 7;
        float4 v = reinterpret_cast<const float4*>(g_acc)[e];
        reinterpret_cast<float4*>(out)[(size_t)__ldg(&g_orig[r]) * 8 + q] = v;
    }
}

// -------- launch 5: restore all-zero scratch state --------------------------
__global__ void k_cleanup(int Nv) {
    int i = blockIdx.x * blockDim.x + threadIdx.x;
    int stride = gridDim.x * blockDim.x;
    for (int e = i; e < Nv; e += stride) g_grid[g_flat[e]] = 0;
    for (int e = i; e < NBUCK; e += stride) g_hist[e] = 0;
    if (i < 2 * CIN) g_stats[i] = 0.f;
    float4 z4 = make_float4(0.f, 0.f, 0.f, 0.f);
    int total4 = Nv * (CIN / 4);
    for (int e = i; e < total4; e += stride)
        reinterpret_cast<float4*>(g_acc)[e] = z4;
}

// -------- launch ------------------------------------------------------------
extern "C" void kernel_launch(void* const* d_in, const int* in_sizes, int n_in,
                              void* d_out, int out_size) {
    const float* feats  = (const float*)d_in[0];   // [N, 32]
    const int*   coords = (const int*)d_in[1];     // [N, 4]
    const float* gamma  = (const float*)d_in[2];   // [32]
    const float* beta   = (const float*)d_in[3];   // [32]
    const float* weight = (const float*)d_in[4];   // [125, 32, 32]
    float* out = (float*)d_out;                    // [N, 32]

    int Nv = in_sizes[0] / CIN;
    if (Nv > NMAX) Nv = NMAX;

    k_scatter_stats<<<1024, 256>>>(feats, coords, Nv);               // 0
    k_scan<<<1, 1024>>>();                                           // 1
    k_rank_norm<<<(Nv + 255) / 256, 256>>>(feats, gamma, beta, Nv);  // 2
    dim3 gc((Nv + SITES_PER_BLOCK - 1) / SITES_PER_BLOCK, KVOL);
    k_conv<<<gc, 256>>>(weight, Nv);                                 // 3 (profiled)
    k_permute<<<(Nv * (CIN / 4) + 255) / 256, 256>>>(out, Nv);       // 4
    k_cleanup<<<2048, 256>>>(Nv);                                    // 5
}

// round 13
// speedup vs baseline: 1.8137x; 1.8137x over previous
#include <cuda_runtime.h>
#include <cstdint>

// Problem constants (fixed by the reference).
#define BB   4
#define DD   128
#define HH   128
#define WW   128
#define NMAX 500000
#define CIN  32
#define COUT 32
#define KVOL 125
#define GRID_SZ (BB * DD * HH * WW)   // 8,388,608
#define NBUCK (GRID_SZ / 512)         // 16384 buckets of 512 voxels (4 x-rows)
#define EPSV 1e-4f
#define FULLMASK 0xffffffffu
#define SITES_PER_BLOCK 2048          // 8 warps x 256 sites each

// -------- device scratch (allocation-free: static __device__ globals) --------
// g_grid holds rank+1 (0 = inactive). Device globals are zero-initialized at
// module load; k_cleanup restores the all-zero state after every run.
__device__ int   g_grid[GRID_SZ];
__device__ int   g_flat[NMAX];             // site (original order) -> flat idx
__device__ int   g_sflat[NMAX];            // rank -> flat idx (bucket-sorted)
__device__ int   g_orig[NMAX];             // rank -> original site row
__device__ int   g_hist[NBUCK];            // bucket histogram / scan bases
__device__ __align__(16) float g_feat[(size_t)NMAX * CIN]; // rank-ordered feats
__device__ __align__(16) float g_acc[(size_t)NMAX * CIN];  // rank-ordered accum
__device__ float g_stats[2 * CIN];

// f32x2 packed FMA — PTX only.
#define FFMA2(acc, f2, w2) \
    asm("fma.rn.f32x2 %0, %1, %2, %3;" : "=l"(acc) : "l"(f2), "l"(w2), "l"(acc))

// -------- launch 0: scatter flat ids + bucket histogram + BN stats ----------
__global__ void k_scatter_stats(const float* __restrict__ x,
                                const int* __restrict__ coords, int Nv) {
    int tid = threadIdx.x;
    int i0 = blockIdx.x * blockDim.x + tid;
    int stride = gridDim.x * blockDim.x;   // multiple of 32

    for (int i = i0; i < Nv; i += stride) {
        int4 c = reinterpret_cast<const int4*>(coords)[i];  // b, z, y, x
        int fl = (((c.x * DD + c.y) * HH + c.z) * WW) + c.w;
        g_flat[i] = fl;
        atomicAdd(&g_hist[fl >> 9], 1);
    }

    // per-channel sum / sumsq (lane channel fixed since stride % 32 == 0)
    __shared__ float ss[8][33];
    __shared__ float ss2[8][33];
    int c = tid & 31;
    int wid = tid >> 5;
    float s = 0.f, s2 = 0.f;
    int total = Nv * CIN;
    for (int e = i0; e < total; e += stride) {
        float v = x[e];
        s += v;
        s2 += v * v;
    }
    ss[wid][c] = s;
    ss2[wid][c] = s2;
    __syncthreads();
    if (tid < 32) {
        float a = 0.f, b = 0.f;
#pragma unroll
        for (int k = 0; k < 8; k++) { a += ss[k][tid]; b += ss2[k][tid]; }
        atomicAdd(&g_stats[tid], a);
        atomicAdd(&g_stats[32 + tid], b);
    }
}

// -------- launch 1: exclusive scan of the bucket histogram ------------------
__global__ void __launch_bounds__(1024) k_scan() {
    __shared__ int part[1024];
    int tid = threadIdx.x;
    int local[16];
    int s = 0;
#pragma unroll
    for (int k = 0; k < 16; k++) { local[k] = s; s += g_hist[tid * 16 + k]; }
    part[tid] = s;
    __syncthreads();
    for (int d = 1; d < 1024; d <<= 1) {
        int v = (tid >= d) ? part[tid - d] : 0;
        __syncthreads();
        part[tid] += v;
        __syncthreads();
    }
    int base = (tid == 0) ? 0 : part[tid - 1];
#pragma unroll
    for (int k = 0; k < 16; k++) g_hist[tid * 16 + k] = base + local[k];
}

// -------- launch 2: assign ranks + grid(rank+1) + normalized rank feats -----
__global__ void __launch_bounds__(256) k_rank_norm(const float* __restrict__ x,
                                                   const float* __restrict__ gamma,
                                                   const float* __restrict__ beta,
                                                   int Nv) {
    __shared__ float sc[32], bi[32];
    __shared__ int rr[256];
    int t = threadIdx.x;
    if (t < 32) {
        float invN = 1.0f / (float)Nv;
        float mean = g_stats[t] * invN;
        float var = g_stats[32 + t] * invN - mean * mean;
        float s = gamma[t] * rsqrtf(var + EPSV);
        sc[t] = s;
        bi[t] = beta[t] - mean * s;
    }
    int i = blockIdx.x * 256 + t;
    if (i < Nv) {
        int fl = g_flat[i];
        int r = atomicAdd(&g_hist[fl >> 9], 1);
        g_sflat[r] = fl;
        g_orig[r] = i;
        g_grid[fl] = r + 1;
        rr[t] = r;
    }
    __syncthreads();
#pragma unroll
    for (int k = 0; k < 8; k++) {
        int e = k * 256 + t;                 // float4 unit within block's span
        int slot = e >> 3, q = e & 7;
        int ii = blockIdx.x * 256 + slot;
        if (ii < Nv) {
            float4 v = __ldg(reinterpret_cast<const float4*>(x) + (size_t)ii * 8 + q);
            int c0 = q * 4;
            float4 o;
            o.x = fmaxf(fmaf(v.x, sc[c0 + 0], bi[c0 + 0]), 0.f);
            o.y = fmaxf(fmaf(v.y, sc[c0 + 1], bi[c0 + 1]), 0.f);
            o.z = fmaxf(fmaf(v.z, sc[c0 + 2], bi[c0 + 2]), 0.f);
            o.w = fmaxf(fmaf(v.w, sc[c0 + 3], bi[c0 + 3]), 0.f);
            reinterpret_cast<float4*>(g_feat)[(size_t)rr[slot] * 8 + q] = o;
        }
    }
}

// -------- launch 3 (PROFILED SLOT): sparse conv, one offset per blockIdx.y --
// Per warp: compact valid pairs from 32-site ballot rounds into a smem ring,
// drain in FULL batches of 4. Each batch stages its 4 feature rows with
// coalesced 128B loads (1 L1 wavefront each, lane=channel) into smem and
// computes from smem via uniform LDS.128 broadcasts (no replication penalty),
// FFMA2 math, then the proven transpose + red.global.add.v4 scatter.
__global__ void __launch_bounds__(256) k_conv(const float* __restrict__ weight,
                                              int Nv) {
    const int o = blockIdx.y;
    const int dz = o / 25 - 2;
    const int dy = (o / 5) % 5 - 2;
    const int dx = o % 5 - 2;
    const int doff = dz * (HH * WW) + dy * WW + dx;
    const int lane = threadIdx.x & 31;
    const int wid = threadIdx.x >> 5;

    __shared__ __align__(16) float ftile[2][8][4][32];   // staged feature rows (8KB)
    __shared__ __align__(16) float ttile[2][8][4][32];   // output transpose    (8KB)
    __shared__ int qsm[8][64];                           // per-warp pair ring  (2KB)

    // Packed weight column: w2[t] = (W[2t][lane], W[2t+1][lane]); once / block.
    unsigned long long w2[16];
    {
        const float* wp = weight + o * (CIN * COUT) + lane;
#pragma unroll
        for (int t = 0; t < 16; t++) {
            float a = __ldg(wp + (2 * t) * COUT);
            float b = __ldg(wp + (2 * t + 1) * COUT);
            asm("mov.b64 %0, {%1, %2};" : "=l"(w2[t]) : "f"(a), "f"(b));
        }
    }

    const int warpBase = blockIdx.x * SITES_PER_BLOCK + wid * 256;
    const int p  = lane >> 3;        // which of the 4 batched pairs this lane stores
    const int c4 = (lane & 7) * 4;   // cout base for the vector RED

    // Preload the 8 rounds' flat ids (coalesced, good MLP).
    int flr[8];
#pragma unroll
    for (int r = 0; r < 8; r++) {
        int s = warpBase + r * 32 + lane;
        flr[r] = __ldg(&g_sflat[s < Nv ? s : (Nv - 1)]);
    }

    int qh = 0, qt = 0, buf = 0;

    // Process one batch of `rem` (1..4) pairs from the queue head.
    auto process4 = [&](int rem) {
        int e0 = qsm[wid][qh & 63];
        int e1 = (rem > 1) ? qsm[wid][(qh + 1) & 63] : e0;
        int e2 = (rem > 2) ? qsm[wid][(qh + 2) & 63] : e0;
        int e3 = (rem > 3) ? qsm[wid][(qh + 3) & 63] : e0;
        // stage 4 neighbor rows, coalesced: lane = channel, 128B = 1 wavefront
        ftile[buf][wid][0][lane] = g_feat[(size_t)(e0 >> 8) * CIN + lane];
        ftile[buf][wid][1][lane] = g_feat[(size_t)(e1 >> 8) * CIN + lane];
        ftile[buf][wid][2][lane] = g_feat[(size_t)(e2 >> 8) * CIN + lane];
        ftile[buf][wid][3][lane] = g_feat[(size_t)(e3 >> 8) * CIN + lane];
        __syncwarp(FULLMASK);
        // compute 4 dots; lane = cout; uniform LDS.128 broadcasts
        unsigned long long a0 = 0ull, a1 = 0ull, a2 = 0ull, a3 = 0ull;
#pragma unroll
        for (int k = 0; k < 8; k++) {
            ulonglong2 q0 = *reinterpret_cast<const ulonglong2*>(&ftile[buf][wid][0][k * 4]);
            ulonglong2 q1 = *reinterpret_cast<const ulonglong2*>(&ftile[buf][wid][1][k * 4]);
            ulonglong2 q2 = *reinterpret_cast<const ulonglong2*>(&ftile[buf][wid][2][k * 4]);
            ulonglong2 q3 = *reinterpret_cast<const ulonglong2*>(&ftile[buf][wid][3][k * 4]);
            FFMA2(a0, q0.x, w2[2 * k]); FFMA2(a0, q0.y, w2[2 * k + 1]);
            FFMA2(a1, q1.x, w2[2 * k]); FFMA2(a1, q1.y, w2[2 * k + 1]);
            FFMA2(a2, q2.x, w2[2 * k]); FFMA2(a2, q2.y, w2[2 * k + 1]);
            FFMA2(a3, q3.x, w2[2 * k]); FFMA2(a3, q3.y, w2[2 * k + 1]);
        }
        float r0, r1, r2, r3;
        {
            float lo, hi;
            asm("mov.b64 {%0, %1}, %2;" : "=f"(lo), "=f"(hi) : "l"(a0)); r0 = lo + hi;
            asm("mov.b64 {%0, %1}, %2;" : "=f"(lo), "=f"(hi) : "l"(a1)); r1 = lo + hi;
            asm("mov.b64 {%0, %1}, %2;" : "=f"(lo), "=f"(hi) : "l"(a2)); r2 = lo + hi;
            asm("mov.b64 {%0, %1}, %2;" : "=f"(lo), "=f"(hi) : "l"(a3)); r3 = lo + hi;
        }
        // transpose through smem: [pair][cout], conflict-free
        ttile[buf][wid][0][lane] = r0;
        ttile[buf][wid][1][lane] = r1;
        ttile[buf][wid][2][lane] = r2;
        ttile[buf][wid][3][lane] = r3;
        __syncwarp(FULLMASK);
        float4 v = *reinterpret_cast<const float4*>(&ttile[buf][wid][p][c4]);
        if (p < rem) {
            int ep = (p == 0) ? e0 : (p == 1) ? e1 : (p == 2) ? e2 : e3;
            float* dst = g_acc + (size_t)(warpBase + (ep & 255)) * COUT + c4;
            asm volatile("red.global.add.v4.f32 [%0], {%1, %2, %3, %4};"
                         :: "l"(dst), "f"(v.x), "f"(v.y), "f"(v.z), "f"(v.w));
        }
        buf ^= 1;
    };

#pragma unroll 1
    for (int r = 0; r < 8; r++) {
        int s = warpBase + r * 32 + lane;
        int fl = flr[r];
        int nidx = -1;
        if (s < Nv) {
            int z = (fl >> 14) & 127, y = (fl >> 7) & 127, x = fl & 127;
            if (((unsigned)(z + dz) < 128u) & ((unsigned)(y + dy) < 128u) &
                ((unsigned)(x + dx) < 128u)) {
                nidx = __ldg(&g_grid[fl + doff]) - 1;   // rank or -1
            }
        }
        unsigned mask = __ballot_sync(FULLMASK, nidx >= 0);
        if (nidx >= 0) {
            int pos = qt + __popc(mask & ((1u << lane) - 1u));
            qsm[wid][pos & 63] = (nidx << 8) | (r * 32 + lane);   // nidx<19b, loc<8b
        }
        qt += __popc(mask);
        __syncwarp(FULLMASK);
        while (qt - qh >= 4) { process4(4); qh += 4; }
    }
    int remq = qt - qh;
    if (remq > 0) process4(remq);
}

// -------- launch 4: permute accumulator back to original row order ----------
__global__ void k_permute(float* __restrict__ out, int Nv) {
    int e = blockIdx.x * blockDim.x + threadIdx.x;  // float4 units
    int total = Nv * (CIN / 4);
    if (e < total) {
        int r = e >> 3, q = e & 7;
        float4 v = reinterpret_cast<const float4*>(g_acc)[e];
        reinterpret_cast<float4*>(out)[(size_t)__ldg(&g_orig[r]) * 8 + q] = v;
    }
}

// -------- launch 5: restore all-zero scratch state --------------------------
__global__ void k_cleanup(int Nv) {
    int i = blockIdx.x * blockDim.x + threadIdx.x;
    int stride = gridDim.x * blockDim.x;
    for (int e = i; e < Nv; e += stride) g_grid[g_flat[e]] = 0;
    for (int e = i; e < NBUCK; e += stride) g_hist[e] = 0;
    if (i < 2 * CIN) g_stats[i] = 0.f;
    float4 z4 = make_float4(0.f, 0.f, 0.f, 0.f);
    int total4 = Nv * (CIN / 4);
    for (int e = i; e < total4; e += stride)
        reinterpret_cast<float4*>(g_acc)[e] = z4;
}

// -------- launch ------------------------------------------------------------
extern "C" void kernel_launch(void* const* d_in, const int* in_sizes, int n_in,
                              void* d_out, int out_size) {
    const float* feats  = (const float*)d_in[0];   // [N, 32]
    const int*   coords = (const int*)d_in[1];     // [N, 4]
    const float* gamma  = (const float*)d_in[2];   // [32]
    const float* beta   = (const float*)d_in[3];   // [32]
    const float* weight = (const float*)d_in[4];   // [125, 32, 32]
    float* out = (float*)d_out;                    // [N, 32]

    int Nv = in_sizes[0] / CIN;
    if (Nv > NMAX) Nv = NMAX;

    k_scatter_stats<<<1024, 256>>>(feats, coords, Nv);               // 0
    k_scan<<<1, 1024>>>();                                           // 1
    k_rank_norm<<<(Nv + 255) / 256, 256>>>(feats, gamma, beta, Nv);  // 2
    dim3 gc((Nv + SITES_PER_BLOCK - 1) / SITES_PER_BLOCK, KVOL);
    k_conv<<<gc, 256>>>(weight, Nv);                                 // 3 (profiled)
    k_permute<<<(Nv * (CIN / 4) + 255) / 256, 256>>>(out, Nv);       // 4
    k_cleanup<<<2048, 256>>>(Nv);                                    // 5
}